// round 3
// baseline (speedup 1.0000x reference)
#include <cuda_runtime.h>
#include <stdint.h>

#define NN_MAX 50000
#define E_MAX  800000
#define D_IN 128
#define D_RNI 32
#define D_H0 160
#define H 256

// ---------------- scratch (static device globals; no allocs allowed) --------
__device__ __align__(16) float g_h0 [NN_MAX * D_H0];
__device__ __align__(16) float g_xt [NN_MAX * H];
__device__ __align__(16) float g_agg[NN_MAX * H];
__device__ __align__(16) float g_dis[NN_MAX];
__device__ __align__(16) int   g_deg[NN_MAX];
__device__ __align__(16) int   g_rowstart[NN_MAX];
__device__ __align__(16) int   g_cursor[NN_MAX];
__device__ __align__(16) int   g_csr_src[E_MAX];
__device__ int g_is64;

// ---------------- edge-index dtype detection ---------------------------------
// Reference uses int64 edge_index but the harness may coerce to int32.
// Sample the buffer as int64: genuine int64 indices are all in [0, n);
// int32 data reinterpreted as int64 yields lo + hi*2^32 >= 2^32 (hi is a
// random node id, ==0 with p ~2e-5; 512 samples cannot all pass).
__global__ void detect_kernel(const void* __restrict__ ei, int n) {
    if (threadIdx.x == 0 && blockIdx.x == 0) {
        const long long* p = (const long long*)ei;
        int ok = 1;
        for (int i = 0; i < 512; i++) {
            long long v = p[i];             // within first 4KB: safe either way
            if (v < 0 || v >= (long long)n) { ok = 0; break; }
        }
        g_is64 = ok;
    }
}

__device__ __forceinline__ int load_idx(const void* ei, long long i, int is64) {
    return is64 ? (int)((const long long*)ei)[i] : ((const int*)ei)[i];
}

// ---------------- small kernels ----------------------------------------------
__global__ void concat_kernel(const float* __restrict__ x, const float* __restrict__ rni,
                              float* __restrict__ h0, int n) {
    int idx = blockIdx.x * blockDim.x + threadIdx.x;
    int total = n * D_H0;
    if (idx >= total) return;
    int node = idx / D_H0;
    int c = idx - node * D_H0;
    h0[idx] = (c < D_IN) ? x[node * D_IN + c] : rni[node * D_RNI + (c - D_IN)];
}

__global__ void zero_deg_kernel(int* __restrict__ deg, int n) {
    int idx = blockIdx.x * blockDim.x + threadIdx.x;
    if (idx < n) deg[idx] = 0;
}

__global__ void count_deg_kernel(const void* __restrict__ ei, int* __restrict__ deg,
                                 int e, int n) {
    int idx = blockIdx.x * blockDim.x + threadIdx.x;
    if (idx >= e) return;
    int is64 = g_is64;
    int d = load_idx(ei, (long long)e + idx, is64);   // dst row
    if (d >= 0 && d < n) atomicAdd(&deg[d], 1);
}

__global__ void dis_kernel(const int* __restrict__ deg, float* __restrict__ dis, int n) {
    int idx = blockIdx.x * blockDim.x + threadIdx.x;
    if (idx < n) dis[idx] = rsqrtf((float)deg[idx] + 1.0f);
}

// single-block exclusive scan of deg -> row_start (and copy into cursor)
__global__ void scan_kernel(const int* __restrict__ deg, int* __restrict__ row_start,
                            int* __restrict__ cursor, int n) {
    __shared__ int sh[1024];
    __shared__ int carry_sh;
    int tid = threadIdx.x;
    if (tid == 0) carry_sh = 0;
    __syncthreads();
    for (int base = 0; base < n; base += 1024) {
        int i = base + tid;
        int v = (i < n) ? deg[i] : 0;
        sh[tid] = v;
        __syncthreads();
        for (int off = 1; off < 1024; off <<= 1) {
            int t = (tid >= off) ? sh[tid - off] : 0;
            __syncthreads();
            sh[tid] += t;
            __syncthreads();
        }
        int carry = carry_sh;
        if (i < n) {
            int ex = carry + sh[tid] - v;
            row_start[i] = ex;
            cursor[i] = ex;
        }
        __syncthreads();
        if (tid == 0) carry_sh = carry + sh[1023];
        __syncthreads();
    }
}

__global__ void csr_fill_kernel(const void* __restrict__ ei,
                                int* __restrict__ cursor, int* __restrict__ csr_src,
                                int e, int n) {
    int idx = blockIdx.x * blockDim.x + threadIdx.x;
    if (idx >= e) return;
    int is64 = g_is64;
    int d = load_idx(ei, (long long)e + idx, is64);
    int s = load_idx(ei, idx, is64);
    if (d < 0 || d >= n || s < 0 || s >= n) return;
    int p = atomicAdd(&cursor[d], 1);
    if (p >= 0 && p < E_MAX) csr_src[p] = s;
}

// gather-aggregate: one block per dst node, 256 threads = 256 output columns.
// agg[d][c] = dis[d] * ( sum_{s in N(d)} xt[s][c]*dis[s] + xt[d][c]*dis[d] ) + bias[c]
__global__ void gather_kernel(const float* __restrict__ xt, const float* __restrict__ dis,
                              const int* __restrict__ row_start, const int* __restrict__ deg,
                              const int* __restrict__ csr_src, const float* __restrict__ bias,
                              float* __restrict__ agg, int n) {
    int node = blockIdx.x;
    int c = threadIdx.x;
    int start = row_start[node];
    int d = deg[node];
    float acc = 0.0f;
    int s = (d > 0) ? __ldg(&csr_src[start]) : 0;
    for (int j = 0; j < d; j++) {
        int s_next = (j + 1 < d) ? __ldg(&csr_src[start + j + 1]) : 0;
        float w = __ldg(&dis[s]);
        acc = fmaf(__ldg(&xt[(size_t)s * H + c]), w, acc);
        s = s_next;
    }
    float dd = dis[node];
    float self = xt[(size_t)node * H + c];
    agg[(size_t)node * H + c] = fmaf(dd, fmaf(self, dd, acc), bias[c]);
}

// ---------------- SGEMM: C[M,N] = op(A[M,K]) @ B[K,N] (+bias) ----------------
template<bool RELU_IN, bool ADD_BIAS>
__global__ void sgemm_kernel(const float* __restrict__ A, const float* __restrict__ B,
                             const float* __restrict__ bias, float* __restrict__ C,
                             int M, int N, int K) {
    __shared__ float As[16][68];   // [k][m], padded
    __shared__ float Bs[16][64];   // [k][n]

    int tid = threadIdx.x;
    int bm = blockIdx.y * 64;
    int bn = blockIdx.x * 64;
    int ty = tid >> 4;
    int tx = tid & 15;

    int arow  = tid >> 2;
    int acol4 = (tid & 3) << 2;
    int brow  = tid >> 4;
    int bcol4 = (tid & 15) << 2;

    float acc[4][4];
#pragma unroll
    for (int i = 0; i < 4; i++)
#pragma unroll
        for (int j = 0; j < 4; j++) acc[i][j] = 0.0f;

    for (int k0 = 0; k0 < K; k0 += 16) {
        float4 av = make_float4(0.f, 0.f, 0.f, 0.f);
        int gr = bm + arow;
        if (gr < M)
            av = *reinterpret_cast<const float4*>(A + (size_t)gr * K + k0 + acol4);
        if (RELU_IN) {
            av.x = fmaxf(av.x, 0.f); av.y = fmaxf(av.y, 0.f);
            av.z = fmaxf(av.z, 0.f); av.w = fmaxf(av.w, 0.f);
        }
        As[acol4 + 0][arow] = av.x;
        As[acol4 + 1][arow] = av.y;
        As[acol4 + 2][arow] = av.z;
        As[acol4 + 3][arow] = av.w;

        float4 bv = *reinterpret_cast<const float4*>(B + (size_t)(k0 + brow) * N + bn + bcol4);
        *reinterpret_cast<float4*>(&Bs[brow][bcol4]) = bv;

        __syncthreads();

#pragma unroll
        for (int k = 0; k < 16; k++) {
            float4 a = *reinterpret_cast<const float4*>(&As[k][ty * 4]);
            float4 b = *reinterpret_cast<const float4*>(&Bs[k][tx * 4]);
            float ar4[4] = {a.x, a.y, a.z, a.w};
            float br4[4] = {b.x, b.y, b.z, b.w};
#pragma unroll
            for (int i = 0; i < 4; i++)
#pragma unroll
                for (int j = 0; j < 4; j++)
                    acc[i][j] = fmaf(ar4[i], br4[j], acc[i][j]);
        }
        __syncthreads();
    }

#pragma unroll
    for (int i = 0; i < 4; i++) {
        int r = bm + ty * 4 + i;
        if (r >= M) continue;
        float4 out;
        out.x = acc[i][0]; out.y = acc[i][1]; out.z = acc[i][2]; out.w = acc[i][3];
        if (ADD_BIAS) {
            float4 b = *reinterpret_cast<const float4*>(bias + bn + tx * 4);
            out.x += b.x; out.y += b.y; out.z += b.z; out.w += b.w;
        }
        *reinterpret_cast<float4*>(C + (size_t)r * N + bn + tx * 4) = out;
    }
}

// ---------------- launch ------------------------------------------------------
extern "C" void kernel_launch(void* const* d_in, const int* in_sizes, int n_in,
                              void* d_out, int out_size) {
    const float* x     = (const float*)d_in[0];
    const float* rni   = (const float*)d_in[1];
    const void*  ei    = d_in[2];
    const float* W1    = (const float*)d_in[3];
    const float* b1    = (const float*)d_in[4];
    const float* W2    = (const float*)d_in[5];
    const float* b2    = (const float*)d_in[6];
    const float* Wout  = (const float*)d_in[7];
    const float* bout  = (const float*)d_in[8];
    float* out = (float*)d_out;

    int n = in_sizes[0] / D_IN;
    int e = in_sizes[2] / 2;

    float *h0, *xt, *agg, *dis;
    int *deg, *row_start, *cursor, *csr_src;
    cudaGetSymbolAddress((void**)&h0,        g_h0);
    cudaGetSymbolAddress((void**)&xt,        g_xt);
    cudaGetSymbolAddress((void**)&agg,       g_agg);
    cudaGetSymbolAddress((void**)&dis,       g_dis);
    cudaGetSymbolAddress((void**)&deg,       g_deg);
    cudaGetSymbolAddress((void**)&row_start, g_rowstart);
    cudaGetSymbolAddress((void**)&cursor,    g_cursor);
    cudaGetSymbolAddress((void**)&csr_src,   g_csr_src);

    // preprocessing: dtype detect, concat, degrees, dis, CSR build
    detect_kernel<<<1, 32>>>(ei, n);
    concat_kernel<<<(n * D_H0 + 255) / 256, 256>>>(x, rni, h0, n);
    zero_deg_kernel<<<(n + 255) / 256, 256>>>(deg, n);
    count_deg_kernel<<<(e + 255) / 256, 256>>>(ei, deg, e, n);
    dis_kernel<<<(n + 255) / 256, 256>>>(deg, dis, n);
    scan_kernel<<<1, 1024>>>(deg, row_start, cursor, n);
    csr_fill_kernel<<<(e + 255) / 256, 256>>>(ei, cursor, csr_src, e, n);

    dim3 gemm_grid(H / 64, (n + 63) / 64);

    // layer 1: xt = h0 @ W1 ; agg = gather(xt) + self + b1
    sgemm_kernel<false, false><<<gemm_grid, 256>>>(h0, W1, nullptr, xt, n, H, D_H0);
    gather_kernel<<<n, 256>>>(xt, dis, row_start, deg, csr_src, b1, agg, n);

    // layer 2: xt = relu(agg) @ W2 ; agg = gather(xt) + self + b2
    sgemm_kernel<true, false><<<gemm_grid, 256>>>(agg, W2, nullptr, xt, n, H, H);
    gather_kernel<<<n, 256>>>(xt, dis, row_start, deg, csr_src, b2, agg, n);

    // output: out = relu(agg) @ W_out + b_out
    sgemm_kernel<true, true><<<gemm_grid, 256>>>(agg, Wout, bout, out, n, H, H);
}

// round 4
// speedup vs baseline: 1.2717x; 1.2717x over previous
#include <cuda_runtime.h>
#include <stdint.h>

#define NN_MAX 50000
#define E_MAX  800000
#define D_IN 128
#define D_RNI 32
#define D_H0 160
#define H 256

// ---------------- scratch (static device globals; no allocs allowed) --------
__device__ __align__(16) float g_h0 [NN_MAX * D_H0];
__device__ __align__(16) float g_xt [NN_MAX * H];
__device__ __align__(16) float g_agg[NN_MAX * H];
__device__ __align__(16) float g_dis[NN_MAX];
__device__ __align__(16) int   g_deg[NN_MAX];
__device__ __align__(16) int   g_rowstart[NN_MAX];
__device__ __align__(16) int   g_cursor[NN_MAX];
__device__ __align__(16) int   g_csr_src[E_MAX];
__device__ int g_is64;

// ---------------- edge-index dtype detection ---------------------------------
__global__ void detect_kernel(const void* __restrict__ ei, int n) {
    if (threadIdx.x == 0 && blockIdx.x == 0) {
        const long long* p = (const long long*)ei;
        int ok = 1;
        for (int i = 0; i < 512; i++) {
            long long v = p[i];
            if (v < 0 || v >= (long long)n) { ok = 0; break; }
        }
        g_is64 = ok;
    }
}

__device__ __forceinline__ int load_idx(const void* ei, long long i, int is64) {
    return is64 ? (int)((const long long*)ei)[i] : ((const int*)ei)[i];
}

// ---------------- small kernels ----------------------------------------------
__global__ void concat_kernel(const float* __restrict__ x, const float* __restrict__ rni,
                              float* __restrict__ h0, int n) {
    int idx = blockIdx.x * blockDim.x + threadIdx.x;
    int total = n * D_H0;
    if (idx >= total) return;
    int node = idx / D_H0;
    int c = idx - node * D_H0;
    h0[idx] = (c < D_IN) ? x[node * D_IN + c] : rni[node * D_RNI + (c - D_IN)];
}

__global__ void zero_deg_kernel(int* __restrict__ deg, int n) {
    int idx = blockIdx.x * blockDim.x + threadIdx.x;
    if (idx < n) deg[idx] = 0;
}

__global__ void count_deg_kernel(const void* __restrict__ ei, int* __restrict__ deg,
                                 int e, int n) {
    int idx = blockIdx.x * blockDim.x + threadIdx.x;
    if (idx >= e) return;
    int is64 = g_is64;
    int d = load_idx(ei, (long long)e + idx, is64);
    if (d >= 0 && d < n) atomicAdd(&deg[d], 1);
}

__global__ void dis_kernel(const int* __restrict__ deg, float* __restrict__ dis, int n) {
    int idx = blockIdx.x * blockDim.x + threadIdx.x;
    if (idx < n) dis[idx] = rsqrtf((float)deg[idx] + 1.0f);
}

// warp-shuffle exclusive scan of deg -> row_start (and copy into cursor)
__global__ void scan_kernel(const int* __restrict__ deg, int* __restrict__ row_start,
                            int* __restrict__ cursor, int n) {
    __shared__ int warpsum[32];
    int tid = threadIdx.x;
    int lane = tid & 31;
    int wid = tid >> 5;
    int carry = 0;
    for (int base = 0; base < n; base += 1024) {
        int i = base + tid;
        int v = (i < n) ? deg[i] : 0;
        // inclusive warp scan
        int s = v;
#pragma unroll
        for (int off = 1; off < 32; off <<= 1) {
            int t = __shfl_up_sync(0xffffffff, s, off);
            if (lane >= off) s += t;
        }
        if (lane == 31) warpsum[wid] = s;
        __syncthreads();
        if (wid == 0) {
            int w = warpsum[lane];
#pragma unroll
            for (int off = 1; off < 32; off <<= 1) {
                int t = __shfl_up_sync(0xffffffff, w, off);
                if (lane >= off) w += t;
            }
            warpsum[lane] = w;
        }
        __syncthreads();
        int warp_excl = (wid == 0) ? 0 : warpsum[wid - 1];
        int total = warpsum[31];
        if (i < n) {
            int ex = carry + warp_excl + s - v;
            row_start[i] = ex;
            cursor[i] = ex;
        }
        carry += total;
        __syncthreads();
    }
}

__global__ void csr_fill_kernel(const void* __restrict__ ei,
                                int* __restrict__ cursor, int* __restrict__ csr_src,
                                int e, int n) {
    int idx = blockIdx.x * blockDim.x + threadIdx.x;
    if (idx >= e) return;
    int is64 = g_is64;
    int d = load_idx(ei, (long long)e + idx, is64);
    int s = load_idx(ei, idx, is64);
    if (d < 0 || d >= n || s < 0 || s >= n) return;
    int p = atomicAdd(&cursor[d], 1);
    if (p >= 0 && p < E_MAX) csr_src[p] = s;
}

// gather-aggregate: one block per dst node, 256 threads = 256 output columns.
__global__ void gather_kernel(const float* __restrict__ xt, const float* __restrict__ dis,
                              const int* __restrict__ row_start, const int* __restrict__ deg,
                              const int* __restrict__ csr_src, const float* __restrict__ bias,
                              float* __restrict__ agg, int n) {
    int node = blockIdx.x;
    int c = threadIdx.x;
    int start = row_start[node];
    int d = deg[node];
    float acc = 0.0f;
    int s = (d > 0) ? __ldg(&csr_src[start]) : 0;
    for (int j = 0; j < d; j++) {
        int s_next = (j + 1 < d) ? __ldg(&csr_src[start + j + 1]) : 0;
        float w = __ldg(&dis[s]);
        acc = fmaf(__ldg(&xt[(size_t)s * H + c]), w, acc);
        s = s_next;
    }
    float dd = dis[node];
    float self = xt[(size_t)node * H + c];
    agg[(size_t)node * H + c] = fmaf(dd, fmaf(self, dd, acc), bias[c]);
}

// ---------------- tf32x3 tensor-core GEMM ------------------------------------
// C[M,N] = op(A[M,K]) @ B[K,N] (+bias). BM=128, BN=128, BK=16, 256 threads.
// 8 warps: 4 (m) x 2 (n); warp tile 32x64 = 2 x 8 m16n8k8 fragments.
// a = hi + lo (tf32 split); D += hi*hi + hi*lo + lo*hi  (error ~ eps^2).

__device__ __forceinline__ uint32_t f2tf(float f) {
    uint32_t u;
    asm("cvt.rna.tf32.f32 %0, %1;" : "=r"(u) : "f"(f));
    return u;
}

__device__ __forceinline__ void split_tf32(float v, uint32_t& hi, uint32_t& lo) {
    hi = f2tf(v);
    lo = __float_as_uint(v - __uint_as_float(hi));
}

__device__ __forceinline__ void mma_tf32(float (&d)[4], const uint32_t (&a)[4],
                                         const uint32_t (&b)[2]) {
    asm("mma.sync.aligned.m16n8k8.row.col.f32.tf32.tf32.f32 "
        "{%0,%1,%2,%3}, {%4,%5,%6,%7}, {%8,%9}, {%0,%1,%2,%3};"
        : "+f"(d[0]), "+f"(d[1]), "+f"(d[2]), "+f"(d[3])
        : "r"(a[0]), "r"(a[1]), "r"(a[2]), "r"(a[3]), "r"(b[0]), "r"(b[1]));
}

#define APAD 20    // As row stride (16 + 4): conflict-free fragment reads
#define BPAD 136   // Bs row stride (128 + 8): conflict-free fragment reads

template<bool RELU_IN, bool ADD_BIAS>
__global__ void __launch_bounds__(256, 2)
mma_gemm(const float* __restrict__ A, const float* __restrict__ B,
         const float* __restrict__ bias, float* __restrict__ C,
         int M, int N, int K) {
    __shared__ uint32_t As_hi[128 * APAD];
    __shared__ uint32_t As_lo[128 * APAD];
    __shared__ uint32_t Bs_hi[16 * BPAD];
    __shared__ uint32_t Bs_lo[16 * BPAD];

    const int tid  = threadIdx.x;
    const int lane = tid & 31;
    const int warp = tid >> 5;
    const int wm = warp & 3;          // 0..3 (m), warp tile 32 rows
    const int wn = warp >> 2;         // 0..1 (n), warp tile 64 cols
    const int g = lane >> 2;          // groupID
    const int t = lane & 3;           // threadID in group
    const int bm = blockIdx.y * 128;
    const int bn = blockIdx.x * 128;

    float acc[2][8][4];
#pragma unroll
    for (int mi = 0; mi < 2; mi++)
#pragma unroll
        for (int ni = 0; ni < 8; ni++)
#pragma unroll
            for (int r = 0; r < 4; r++) acc[mi][ni][r] = 0.0f;

    // per-thread load slots: A tile = 128x16 = 512 float4 (2/thread),
    //                        B tile = 16x128 = 512 float4 (2/thread)
    float4 pa[2], pb[2];

    auto load_tiles = [&](int k0) {
#pragma unroll
        for (int i = 0; i < 2; i++) {
            int idx = i * 256 + tid;
            int m  = idx >> 2;
            int kq = (idx & 3) << 2;
            int gm = bm + m;
            pa[i] = (gm < M) ? *reinterpret_cast<const float4*>(A + (size_t)gm * K + k0 + kq)
                             : make_float4(0.f, 0.f, 0.f, 0.f);
        }
#pragma unroll
        for (int i = 0; i < 2; i++) {
            int idx = i * 256 + tid;
            int kr = idx >> 5;
            int nq = (idx & 31) << 2;
            pb[i] = *reinterpret_cast<const float4*>(B + (size_t)(k0 + kr) * N + bn + nq);
        }
    };

    auto store_tiles = [&]() {
#pragma unroll
        for (int i = 0; i < 2; i++) {
            int idx = i * 256 + tid;
            int m  = idx >> 2;
            int kq = (idx & 3) << 2;
            float4 v = pa[i];
            if (RELU_IN) {
                v.x = fmaxf(v.x, 0.f); v.y = fmaxf(v.y, 0.f);
                v.z = fmaxf(v.z, 0.f); v.w = fmaxf(v.w, 0.f);
            }
            uint4 h, l;
            split_tf32(v.x, h.x, l.x); split_tf32(v.y, h.y, l.y);
            split_tf32(v.z, h.z, l.z); split_tf32(v.w, h.w, l.w);
            *reinterpret_cast<uint4*>(&As_hi[m * APAD + kq]) = h;
            *reinterpret_cast<uint4*>(&As_lo[m * APAD + kq]) = l;
        }
#pragma unroll
        for (int i = 0; i < 2; i++) {
            int idx = i * 256 + tid;
            int kr = idx >> 5;
            int nq = (idx & 31) << 2;
            float4 v = pb[i];
            uint4 h, l;
            split_tf32(v.x, h.x, l.x); split_tf32(v.y, h.y, l.y);
            split_tf32(v.z, h.z, l.z); split_tf32(v.w, h.w, l.w);
            *reinterpret_cast<uint4*>(&Bs_hi[kr * BPAD + nq]) = h;
            *reinterpret_cast<uint4*>(&Bs_lo[kr * BPAD + nq]) = l;
        }
    };

    load_tiles(0);

    for (int k0 = 0; k0 < K; k0 += 16) {
        store_tiles();
        __syncthreads();
        if (k0 + 16 < K) load_tiles(k0 + 16);   // overlap next loads with compute

#pragma unroll
        for (int kk = 0; kk < 16; kk += 8) {
            uint32_t ah[2][4], al[2][4];
#pragma unroll
            for (int mi = 0; mi < 2; mi++) {
                int r0 = (wm * 32 + mi * 16 + g) * APAD;
                int r1 = r0 + 8 * APAD;
                int c0 = kk + t;
                int c1 = c0 + 4;
                ah[mi][0] = As_hi[r0 + c0]; ah[mi][1] = As_hi[r1 + c0];
                ah[mi][2] = As_hi[r0 + c1]; ah[mi][3] = As_hi[r1 + c1];
                al[mi][0] = As_lo[r0 + c0]; al[mi][1] = As_lo[r1 + c0];
                al[mi][2] = As_lo[r0 + c1]; al[mi][3] = As_lo[r1 + c1];
            }
#pragma unroll
            for (int ni = 0; ni < 8; ni++) {
                int ncol = wn * 64 + ni * 8 + g;
                int kr0 = (kk + t) * BPAD;
                int kr1 = kr0 + 4 * BPAD;
                uint32_t bh[2] = { Bs_hi[kr0 + ncol], Bs_hi[kr1 + ncol] };
                uint32_t bl[2] = { Bs_lo[kr0 + ncol], Bs_lo[kr1 + ncol] };
#pragma unroll
                for (int mi = 0; mi < 2; mi++) {
                    mma_tf32(acc[mi][ni], ah[mi], bh);
                    mma_tf32(acc[mi][ni], ah[mi], bl);
                    mma_tf32(acc[mi][ni], al[mi], bh);
                }
            }
        }
        __syncthreads();
    }

    // epilogue
#pragma unroll
    for (int mi = 0; mi < 2; mi++) {
#pragma unroll
        for (int ni = 0; ni < 8; ni++) {
            int row = bm + wm * 32 + mi * 16 + g;
            int col = bn + wn * 64 + ni * 8 + t * 2;
            float bx = 0.f, by = 0.f;
            if (ADD_BIAS) {
                float2 bb = *reinterpret_cast<const float2*>(bias + col);
                bx = bb.x; by = bb.y;
            }
            if (row < M) {
                float2 v = make_float2(acc[mi][ni][0] + bx, acc[mi][ni][1] + by);
                *reinterpret_cast<float2*>(C + (size_t)row * N + col) = v;
            }
            int row2 = row + 8;
            if (row2 < M) {
                float2 v = make_float2(acc[mi][ni][2] + bx, acc[mi][ni][3] + by);
                *reinterpret_cast<float2*>(C + (size_t)row2 * N + col) = v;
            }
        }
    }
}

// ---------------- launch ------------------------------------------------------
extern "C" void kernel_launch(void* const* d_in, const int* in_sizes, int n_in,
                              void* d_out, int out_size) {
    const float* x     = (const float*)d_in[0];
    const float* rni   = (const float*)d_in[1];
    const void*  ei    = d_in[2];
    const float* W1    = (const float*)d_in[3];
    const float* b1    = (const float*)d_in[4];
    const float* W2    = (const float*)d_in[5];
    const float* b2    = (const float*)d_in[6];
    const float* Wout  = (const float*)d_in[7];
    const float* bout  = (const float*)d_in[8];
    float* out = (float*)d_out;

    int n = in_sizes[0] / D_IN;
    int e = in_sizes[2] / 2;

    float *h0, *xt, *agg, *dis;
    int *deg, *row_start, *cursor, *csr_src;
    cudaGetSymbolAddress((void**)&h0,        g_h0);
    cudaGetSymbolAddress((void**)&xt,        g_xt);
    cudaGetSymbolAddress((void**)&agg,       g_agg);
    cudaGetSymbolAddress((void**)&dis,       g_dis);
    cudaGetSymbolAddress((void**)&deg,       g_deg);
    cudaGetSymbolAddress((void**)&row_start, g_rowstart);
    cudaGetSymbolAddress((void**)&cursor,    g_cursor);
    cudaGetSymbolAddress((void**)&csr_src,   g_csr_src);

    // preprocessing: dtype detect, concat, degrees, dis, CSR build
    detect_kernel<<<1, 32>>>(ei, n);
    concat_kernel<<<(n * D_H0 + 255) / 256, 256>>>(x, rni, h0, n);
    zero_deg_kernel<<<(n + 255) / 256, 256>>>(deg, n);
    count_deg_kernel<<<(e + 255) / 256, 256>>>(ei, deg, e, n);
    dis_kernel<<<(n + 255) / 256, 256>>>(deg, dis, n);
    scan_kernel<<<1, 1024>>>(deg, row_start, cursor, n);
    csr_fill_kernel<<<(e + 255) / 256, 256>>>(ei, cursor, csr_src, e, n);

    dim3 gemm_grid(H / 128, (n + 127) / 128);

    // layer 1: xt = h0 @ W1 ; agg = gather(xt) + self + b1
    mma_gemm<false, false><<<gemm_grid, 256>>>(h0, W1, nullptr, xt, n, H, D_H0);
    gather_kernel<<<n, 256>>>(xt, dis, row_start, deg, csr_src, b1, agg, n);

    // layer 2: xt = relu(agg) @ W2 ; agg = gather(xt) + self + b2
    mma_gemm<true, false><<<gemm_grid, 256>>>(agg, W2, nullptr, xt, n, H, H);
    gather_kernel<<<n, 256>>>(xt, dis, row_start, deg, csr_src, b2, agg, n);

    // output: out = relu(agg) @ W_out + b_out
    mma_gemm<true, true><<<gemm_grid, 256>>>(agg, Wout, bout, out, n, H, H);
}

// round 5
// speedup vs baseline: 1.7682x; 1.3904x over previous
#include <cuda_runtime.h>
#include <stdint.h>

#define NN_MAX 50000
#define E_MAX  800000
#define D_IN 128
#define D_RNI 32
#define D_H0 160
#define H 256

// ---------------- scratch (static device globals; no allocs allowed) --------
__device__ __align__(16) float g_xt [NN_MAX * H];
__device__ __align__(16) float g_agg[NN_MAX * H];
__device__ __align__(16) float g_dis[NN_MAX];
__device__ __align__(16) int   g_deg[NN_MAX];
__device__ __align__(16) int   g_rowstart[NN_MAX];
__device__ __align__(16) int   g_cursor[NN_MAX];
__device__ __align__(16) int   g_csr_src[E_MAX];
__device__ int g_is64;

// ---------------- edge-index dtype detection ---------------------------------
__global__ void detect_kernel(const void* __restrict__ ei, int n) {
    if (threadIdx.x == 0 && blockIdx.x == 0) {
        const long long* p = (const long long*)ei;
        int ok = 1;
        for (int i = 0; i < 512; i++) {
            long long v = p[i];
            if (v < 0 || v >= (long long)n) { ok = 0; break; }
        }
        g_is64 = ok;
    }
}

__device__ __forceinline__ int load_idx(const void* ei, long long i, int is64) {
    return is64 ? (int)((const long long*)ei)[i] : ((const int*)ei)[i];
}

__global__ void count_deg_kernel(const void* __restrict__ ei, int* __restrict__ deg,
                                 int e, int n) {
    int idx = blockIdx.x * blockDim.x + threadIdx.x;
    if (idx >= e) return;
    int is64 = g_is64;
    int d = load_idx(ei, (long long)e + idx, is64);
    if (d >= 0 && d < n) atomicAdd(&deg[d], 1);
}

// warp-shuffle exclusive scan of deg -> row_start + cursor; also dis = rsqrt(deg+1)
__global__ void scan_dis_kernel(const int* __restrict__ deg, int* __restrict__ row_start,
                                int* __restrict__ cursor, float* __restrict__ dis, int n) {
    __shared__ int warpsum[32];
    int tid = threadIdx.x;
    int lane = tid & 31;
    int wid = tid >> 5;
    int carry = 0;
    for (int base = 0; base < n; base += 1024) {
        int i = base + tid;
        int v = (i < n) ? deg[i] : 0;
        int s = v;
#pragma unroll
        for (int off = 1; off < 32; off <<= 1) {
            int t = __shfl_up_sync(0xffffffff, s, off);
            if (lane >= off) s += t;
        }
        if (lane == 31) warpsum[wid] = s;
        __syncthreads();
        if (wid == 0) {
            int w = warpsum[lane];
#pragma unroll
            for (int off = 1; off < 32; off <<= 1) {
                int t = __shfl_up_sync(0xffffffff, w, off);
                if (lane >= off) w += t;
            }
            warpsum[lane] = w;
        }
        __syncthreads();
        int warp_excl = (wid == 0) ? 0 : warpsum[wid - 1];
        int total = warpsum[31];
        if (i < n) {
            int ex = carry + warp_excl + s - v;
            row_start[i] = ex;
            cursor[i] = ex;
            dis[i] = rsqrtf((float)v + 1.0f);
        }
        carry += total;
        __syncthreads();
    }
}

__global__ void csr_fill_kernel(const void* __restrict__ ei,
                                int* __restrict__ cursor, int* __restrict__ csr_src,
                                int e, int n) {
    int idx = blockIdx.x * blockDim.x + threadIdx.x;
    if (idx >= e) return;
    int is64 = g_is64;
    int d = load_idx(ei, (long long)e + idx, is64);
    int s = load_idx(ei, idx, is64);
    if (d < 0 || d >= n || s < 0 || s >= n) return;
    int p = atomicAdd(&cursor[d], 1);
    if (p >= 0 && p < E_MAX) csr_src[p] = s;
}

// gather-aggregate: 64 threads per node (float4 columns), 4 nodes per block.
// agg[d][:] = dis[d]*( sum_s xt[s][:]*dis[s] + xt[d][:]*dis[d] ) + bias
__global__ void gather_kernel(const float* __restrict__ xt, const float* __restrict__ dis,
                              const int* __restrict__ row_start, const int* __restrict__ deg,
                              const int* __restrict__ csr_src, const float* __restrict__ bias,
                              float* __restrict__ agg, int n) {
    int node = blockIdx.x * 4 + (threadIdx.x >> 6);
    int c4 = threadIdx.x & 63;              // float4 column 0..63
    if (node >= n) return;
    int start = row_start[node];
    int d = deg[node];
    const float4* xt4 = reinterpret_cast<const float4*>(xt);

    float4 a0 = make_float4(0.f, 0.f, 0.f, 0.f);
    float4 a1 = make_float4(0.f, 0.f, 0.f, 0.f);
    int j = 0;
    for (; j + 2 <= d; j += 2) {
        int s0 = __ldg(&csr_src[start + j]);
        int s1 = __ldg(&csr_src[start + j + 1]);
        float w0 = __ldg(&dis[s0]);
        float w1 = __ldg(&dis[s1]);
        float4 v0 = __ldg(&xt4[(size_t)s0 * 64 + c4]);
        float4 v1 = __ldg(&xt4[(size_t)s1 * 64 + c4]);
        a0.x = fmaf(v0.x, w0, a0.x); a0.y = fmaf(v0.y, w0, a0.y);
        a0.z = fmaf(v0.z, w0, a0.z); a0.w = fmaf(v0.w, w0, a0.w);
        a1.x = fmaf(v1.x, w1, a1.x); a1.y = fmaf(v1.y, w1, a1.y);
        a1.z = fmaf(v1.z, w1, a1.z); a1.w = fmaf(v1.w, w1, a1.w);
    }
    if (j < d) {
        int s0 = __ldg(&csr_src[start + j]);
        float w0 = __ldg(&dis[s0]);
        float4 v0 = __ldg(&xt4[(size_t)s0 * 64 + c4]);
        a0.x = fmaf(v0.x, w0, a0.x); a0.y = fmaf(v0.y, w0, a0.y);
        a0.z = fmaf(v0.z, w0, a0.z); a0.w = fmaf(v0.w, w0, a0.w);
    }
    a0.x += a1.x; a0.y += a1.y; a0.z += a1.z; a0.w += a1.w;

    float dd = dis[node];
    float4 self = xt4[(size_t)node * 64 + c4];
    float4 b = reinterpret_cast<const float4*>(bias)[c4];
    float4 r;
    r.x = fmaf(dd, fmaf(self.x, dd, a0.x), b.x);
    r.y = fmaf(dd, fmaf(self.y, dd, a0.y), b.y);
    r.z = fmaf(dd, fmaf(self.z, dd, a0.z), b.z);
    r.w = fmaf(dd, fmaf(self.w, dd, a0.w), b.w);
    reinterpret_cast<float4*>(agg)[(size_t)node * 64 + c4] = r;
}

// ---------------- tf32x3 tensor-core GEMM ------------------------------------
// C[M,N] = op(A[M,K]) @ B[K,N] (+bias). BM=128, BN=128, BK=16, 256 threads.
// SPLIT_A: A is the virtual concat [x (128 cols) | rni (32 cols)], K=160.

__device__ __forceinline__ uint32_t f2tf(float f) {
    uint32_t u;
    asm("cvt.rna.tf32.f32 %0, %1;" : "=r"(u) : "f"(f));
    return u;
}

__device__ __forceinline__ void split_tf32(float v, uint32_t& hi, uint32_t& lo) {
    hi = f2tf(v);
    lo = __float_as_uint(v - __uint_as_float(hi));
}

__device__ __forceinline__ void mma_tf32(float (&d)[4], const uint32_t (&a)[4],
                                         const uint32_t (&b)[2]) {
    asm("mma.sync.aligned.m16n8k8.row.col.f32.tf32.tf32.f32 "
        "{%0,%1,%2,%3}, {%4,%5,%6,%7}, {%8,%9}, {%0,%1,%2,%3};"
        : "+f"(d[0]), "+f"(d[1]), "+f"(d[2]), "+f"(d[3])
        : "r"(a[0]), "r"(a[1]), "r"(a[2]), "r"(a[3]), "r"(b[0]), "r"(b[1]));
}

#define APAD 20
#define BPAD 136

template<bool SPLIT_A, bool RELU_IN, bool ADD_BIAS>
__global__ void __launch_bounds__(256, 2)
mma_gemm(const float* __restrict__ A, const float* __restrict__ A2,
         const float* __restrict__ B,
         const float* __restrict__ bias, float* __restrict__ C,
         int M, int N, int K) {
    __shared__ uint32_t As_hi[128 * APAD];
    __shared__ uint32_t As_lo[128 * APAD];
    __shared__ uint32_t Bs_hi[16 * BPAD];
    __shared__ uint32_t Bs_lo[16 * BPAD];

    const int tid  = threadIdx.x;
    const int lane = tid & 31;
    const int warp = tid >> 5;
    const int wm = warp & 3;
    const int wn = warp >> 2;
    const int g = lane >> 2;
    const int t = lane & 3;
    const int bm = blockIdx.y * 128;
    const int bn = blockIdx.x * 128;

    float acc[2][8][4];
#pragma unroll
    for (int mi = 0; mi < 2; mi++)
#pragma unroll
        for (int ni = 0; ni < 8; ni++)
#pragma unroll
            for (int r = 0; r < 4; r++) acc[mi][ni][r] = 0.0f;

    float4 pa[2], pb[2];

    auto load_tiles = [&](int k0) {
#pragma unroll
        for (int i = 0; i < 2; i++) {
            int idx = i * 256 + tid;
            int m  = idx >> 2;
            int col = k0 + ((idx & 3) << 2);
            int gm = bm + m;
            if (gm < M) {
                if (SPLIT_A) {
                    pa[i] = (col < D_IN)
                        ? *reinterpret_cast<const float4*>(A  + (size_t)gm * D_IN  + col)
                        : *reinterpret_cast<const float4*>(A2 + (size_t)gm * D_RNI + (col - D_IN));
                } else {
                    pa[i] = *reinterpret_cast<const float4*>(A + (size_t)gm * K + col);
                }
            } else {
                pa[i] = make_float4(0.f, 0.f, 0.f, 0.f);
            }
        }
#pragma unroll
        for (int i = 0; i < 2; i++) {
            int idx = i * 256 + tid;
            int kr = idx >> 5;
            int nq = (idx & 31) << 2;
            pb[i] = *reinterpret_cast<const float4*>(B + (size_t)(k0 + kr) * N + bn + nq);
        }
    };

    auto store_tiles = [&]() {
#pragma unroll
        for (int i = 0; i < 2; i++) {
            int idx = i * 256 + tid;
            int m  = idx >> 2;
            int kq = (idx & 3) << 2;
            float4 v = pa[i];
            if (RELU_IN) {
                v.x = fmaxf(v.x, 0.f); v.y = fmaxf(v.y, 0.f);
                v.z = fmaxf(v.z, 0.f); v.w = fmaxf(v.w, 0.f);
            }
            uint4 h, l;
            split_tf32(v.x, h.x, l.x); split_tf32(v.y, h.y, l.y);
            split_tf32(v.z, h.z, l.z); split_tf32(v.w, h.w, l.w);
            *reinterpret_cast<uint4*>(&As_hi[m * APAD + kq]) = h;
            *reinterpret_cast<uint4*>(&As_lo[m * APAD + kq]) = l;
        }
#pragma unroll
        for (int i = 0; i < 2; i++) {
            int idx = i * 256 + tid;
            int kr = idx >> 5;
            int nq = (idx & 31) << 2;
            float4 v = pb[i];
            uint4 h, l;
            split_tf32(v.x, h.x, l.x); split_tf32(v.y, h.y, l.y);
            split_tf32(v.z, h.z, l.z); split_tf32(v.w, h.w, l.w);
            *reinterpret_cast<uint4*>(&Bs_hi[kr * BPAD + nq]) = h;
            *reinterpret_cast<uint4*>(&Bs_lo[kr * BPAD + nq]) = l;
        }
    };

    load_tiles(0);

    for (int k0 = 0; k0 < K; k0 += 16) {
        store_tiles();
        __syncthreads();
        if (k0 + 16 < K) load_tiles(k0 + 16);

#pragma unroll
        for (int kk = 0; kk < 16; kk += 8) {
            uint32_t ah[2][4], al[2][4];
#pragma unroll
            for (int mi = 0; mi < 2; mi++) {
                int r0 = (wm * 32 + mi * 16 + g) * APAD;
                int r1 = r0 + 8 * APAD;
                int c0 = kk + t;
                int c1 = c0 + 4;
                ah[mi][0] = As_hi[r0 + c0]; ah[mi][1] = As_hi[r1 + c0];
                ah[mi][2] = As_hi[r0 + c1]; ah[mi][3] = As_hi[r1 + c1];
                al[mi][0] = As_lo[r0 + c0]; al[mi][1] = As_lo[r1 + c0];
                al[mi][2] = As_lo[r0 + c1]; al[mi][3] = As_lo[r1 + c1];
            }
#pragma unroll
            for (int ni = 0; ni < 8; ni++) {
                int ncol = wn * 64 + ni * 8 + g;
                int kr0 = (kk + t) * BPAD;
                int kr1 = kr0 + 4 * BPAD;
                uint32_t bh[2] = { Bs_hi[kr0 + ncol], Bs_hi[kr1 + ncol] };
                uint32_t bl[2] = { Bs_lo[kr0 + ncol], Bs_lo[kr1 + ncol] };
#pragma unroll
                for (int mi = 0; mi < 2; mi++) {
                    mma_tf32(acc[mi][ni], ah[mi], bh);
                    mma_tf32(acc[mi][ni], ah[mi], bl);
                    mma_tf32(acc[mi][ni], al[mi], bh);
                }
            }
        }
        __syncthreads();
    }

#pragma unroll
    for (int mi = 0; mi < 2; mi++) {
#pragma unroll
        for (int ni = 0; ni < 8; ni++) {
            int row = bm + wm * 32 + mi * 16 + g;
            int col = bn + wn * 64 + ni * 8 + t * 2;
            float bx = 0.f, by = 0.f;
            if (ADD_BIAS) {
                float2 bb = *reinterpret_cast<const float2*>(bias + col);
                bx = bb.x; by = bb.y;
            }
            if (row < M) {
                float2 v = make_float2(acc[mi][ni][0] + bx, acc[mi][ni][1] + by);
                *reinterpret_cast<float2*>(C + (size_t)row * N + col) = v;
            }
            int row2 = row + 8;
            if (row2 < M) {
                float2 v = make_float2(acc[mi][ni][2] + bx, acc[mi][ni][3] + by);
                *reinterpret_cast<float2*>(C + (size_t)row2 * N + col) = v;
            }
        }
    }
}

// ---------------- launch ------------------------------------------------------
extern "C" void kernel_launch(void* const* d_in, const int* in_sizes, int n_in,
                              void* d_out, int out_size) {
    const float* x     = (const float*)d_in[0];
    const float* rni   = (const float*)d_in[1];
    const void*  ei    = d_in[2];
    const float* W1    = (const float*)d_in[3];
    const float* b1    = (const float*)d_in[4];
    const float* W2    = (const float*)d_in[5];
    const float* b2    = (const float*)d_in[6];
    const float* Wout  = (const float*)d_in[7];
    const float* bout  = (const float*)d_in[8];
    float* out = (float*)d_out;

    int n = in_sizes[0] / D_IN;
    int e = in_sizes[2] / 2;

    float *xt, *agg, *dis;
    int *deg, *row_start, *cursor, *csr_src;
    cudaGetSymbolAddress((void**)&xt,        g_xt);
    cudaGetSymbolAddress((void**)&agg,       g_agg);
    cudaGetSymbolAddress((void**)&dis,       g_dis);
    cudaGetSymbolAddress((void**)&deg,       g_deg);
    cudaGetSymbolAddress((void**)&row_start, g_rowstart);
    cudaGetSymbolAddress((void**)&cursor,    g_cursor);
    cudaGetSymbolAddress((void**)&csr_src,   g_csr_src);

    // prep: dtype detect, degree count, scan+dis, CSR fill
    detect_kernel<<<1, 32>>>(ei, n);
    cudaMemsetAsync(deg, 0, (size_t)n * sizeof(int));
    count_deg_kernel<<<(e + 255) / 256, 256>>>(ei, deg, e, n);
    scan_dis_kernel<<<1, 1024>>>(deg, row_start, cursor, dis, n);
    csr_fill_kernel<<<(e + 255) / 256, 256>>>(ei, cursor, csr_src, e, n);

    dim3 gemm_grid(H / 128, (n + 127) / 128);
    int gather_grid = (n + 3) / 4;

    // layer 1: xt = [x|rni] @ W1 ; agg = gather(xt) + self + b1
    mma_gemm<true, false, false><<<gemm_grid, 256>>>(x, rni, W1, nullptr, xt, n, H, D_H0);
    gather_kernel<<<gather_grid, 256>>>(xt, dis, row_start, deg, csr_src, b1, agg, n);

    // layer 2: xt = relu(agg) @ W2 ; agg = gather(xt) + self + b2
    mma_gemm<false, true, false><<<gemm_grid, 256>>>(agg, nullptr, W2, nullptr, xt, n, H, H);
    gather_kernel<<<gather_grid, 256>>>(xt, dis, row_start, deg, csr_src, b2, agg, n);

    // output: out = relu(agg) @ W_out + b_out
    mma_gemm<false, true, true><<<gemm_grid, 256>>>(agg, nullptr, Wout, bout, out, n, H, H);
}